// round 7
// baseline (speedup 1.0000x reference)
#include <cuda_runtime.h>

#define Bz 256
#define Lz 8192
#define EPSf 1e-5f

typedef unsigned long long ull;

// ---------------- packed f32x2 helpers ----------------
__device__ __forceinline__ ull bc2(float v) {
    ull d;
    asm("mov.b64 %0, {%1, %1};" : "=l"(d) : "f"(v));
    return d;
}
__device__ __forceinline__ void upk2(ull v, float& lo, float& hi) {
    asm("mov.b64 {%0, %1}, %2;" : "=f"(lo), "=f"(hi) : "l"(v));
}
__device__ __forceinline__ ull ffma2(ull a, ull b, ull c) {
    ull d;
    asm("fma.rn.f32x2 %0, %1, %2, %3;" : "=l"(d) : "l"(a), "l"(b), "l"(c));
    return d;
}

// ---------------- scratch (no allocs allowed) ----------------
__device__ float g_Meff[Bz * 256];
__device__ float g_W1f[64];
__device__ float g_b1f[16];
__device__ float g_b2f[16];

// ---------------- prep: fold BN params ----------------
__global__ void prep_kernel(const float* __restrict__ wc1, const float* __restrict__ g1,
                            const float* __restrict__ bt1, const float* __restrict__ m1,
                            const float* __restrict__ v1, const float* __restrict__ g2,
                            const float* __restrict__ bt2, const float* __restrict__ m2,
                            const float* __restrict__ v2) {
    int t = threadIdx.x;
    if (t < 64) {
        int d = t >> 2;
        float s1 = g1[d] * rsqrtf(v1[d] + EPSf);
        g_W1f[t] = wc1[t] * s1;
        if ((t & 3) == 0) g_b1f[d] = bt1[d] - m1[d] * s1;
    }
    if (t < 16) {
        float s2 = g2[t] * rsqrtf(v2[t] + EPSf);
        g_b2f[t] = bt2[t] - m2[t] * s2;
    }
}

// triangular index for c<=d
#define TRI(c, d) ((c)*16 - ((c) * ((c) + 1)) / 2 + (d))

// ---------------- gram + attn fused: one CTA per batch ----------------
__global__ void __launch_bounds__(256) gram_attn_kernel(
    const float* __restrict__ x, const float* __restrict__ wc2,
    const float* __restrict__ g2, const float* __restrict__ v2,
    const float* __restrict__ beta_cam) {
    int b = blockIdx.x;
    int tid = threadIdx.x;
    __shared__ float w1fs[64], b1fs[16];
    __shared__ float wsum[8][136];
    __shared__ float gram_s[256];
    __shared__ float As[256];
    if (tid < 64) w1fs[tid] = g_W1f[tid];
    if (tid < 16) b1fs[tid] = g_b1f[tid];
    __syncthreads();

    float acc[136];
#pragma unroll
    for (int t = 0; t < 136; t++) acc[t] = 0.f;

    const float* xb = x + (size_t)b * 4 * Lz;
    for (int it = 0; it < 32; it++) {
        int pos = it * 256 + tid;
        float xv0 = xb[0 * Lz + pos];
        float xv1 = xb[1 * Lz + pos];
        float xv2 = xb[2 * Lz + pos];
        float xv3 = xb[3 * Lz + pos];
        float c0[16];
#pragma unroll
        for (int d = 0; d < 16; d++) {
            float s = b1fs[d];
            s += xv0 * w1fs[d * 4 + 0];
            s += xv1 * w1fs[d * 4 + 1];
            s += xv2 * w1fs[d * 4 + 2];
            s += xv3 * w1fs[d * 4 + 3];
            c0[d] = fmaxf(s, 0.f);
        }
#pragma unroll
        for (int c = 0; c < 16; c++)
#pragma unroll
            for (int d = c; d < 16; d++)
                acc[TRI(c, d)] += c0[c] * c0[d];
    }

    int warp = tid >> 5, lane = tid & 31;
#pragma unroll
    for (int t = 0; t < 136; t++) {
        float v = acc[t];
        v += __shfl_xor_sync(0xffffffffu, v, 16);
        v += __shfl_xor_sync(0xffffffffu, v, 8);
        v += __shfl_xor_sync(0xffffffffu, v, 4);
        v += __shfl_xor_sync(0xffffffffu, v, 2);
        v += __shfl_xor_sync(0xffffffffu, v, 1);
        if (lane == 0) wsum[warp][t] = v;
    }
    __syncthreads();
    if (tid < 136) {
        float s = 0.f;
#pragma unroll
        for (int w = 0; w < 8; w++) s += wsum[w][tid];
        int c = 0, rem = tid;
        while (rem >= 16 - c) { rem -= 16 - c; c++; }
        int d = c + rem;
        gram_s[c * 16 + d] = s;
        if (d != c) gram_s[d * 16 + c] = s;
    }
    __syncthreads();

    // ---- attn: softmax(rowmax - gram) folded into Meff ----
    float g = gram_s[tid];
    float mn = g;
    mn = fminf(mn, __shfl_xor_sync(0xffffffffu, mn, 8, 16));
    mn = fminf(mn, __shfl_xor_sync(0xffffffffu, mn, 4, 16));
    mn = fminf(mn, __shfl_xor_sync(0xffffffffu, mn, 2, 16));
    mn = fminf(mn, __shfl_xor_sync(0xffffffffu, mn, 1, 16));
    float e = expf(mn - g);
    float s = e;
    s += __shfl_xor_sync(0xffffffffu, s, 8, 16);
    s += __shfl_xor_sync(0xffffffffu, s, 4, 16);
    s += __shfl_xor_sync(0xffffffffu, s, 2, 16);
    s += __shfl_xor_sync(0xffffffffu, s, 1, 16);
    float beta = beta_cam[0];
    As[tid] = beta * (e / s);
    __syncthreads();

    int c = tid >> 4, d = tid & 15;
    float s2c = g2[c] * rsqrtf(v2[c] + EPSf);
    float a = wc2[c * 16 + d];
#pragma unroll
    for (int e2 = 0; e2 < 16; e2++)
        a += wc2[c * 16 + e2] * As[e2 * 16 + d];
    g_Meff[b * 256 + tid] = s2c * a;
}

// ---------------- fused main kernel ----------------
#define TILE 512
#define XS_N 648          // x tile + halo, swizzled (raw 607 -> swz 644)
#define FE_STR 704        // fea0 per-channel stride (raw 557 -> SWZ4 693), 16B-mult
#define ST_STR 544        // stage per-channel stride (raw 511 -> swz 542)
#define SWZ(i) ((i) + ((i) >> 4))
#define SWZ4(i) ((i) + (((i) >> 4) << 2))

#define OFF_XS 0
#define OFF_F0 (OFF_XS + 4 * XS_N)            // 2592
#define OFF_W00 (OFF_F0 + 8 * FE_STR)         // 8224 (pair-ordered, 1024 floats)
#define OFF_W01 (OFF_W00 + 1024)              // 9248
#define OFF_W02 (OFF_W01 + 1024)              // 10272
#define OFF_ME (OFF_W02 + 1024)               // 11296
#define OFF_STG (OFF_ME + 256)                // 11552
#define OFF_W1F (OFF_STG + 16 * ST_STR)       // 20256
#define OFF_B1F (OFF_W1F + 64)                // 20320
#define OFF_B2F (OFF_B1F + 16)                // 20336
#define OFF_B00 (OFF_B2F + 16)                // 20352
#define OFF_B01 (OFF_B00 + 8)                 // 20360
#define OFF_B02 (OFF_B01 + 8)                 // 20368
#define SMEM_FLOATS (OFF_B02 + 8)             // 20376 floats = 81504 B

__global__ void __launch_bounds__(256, 2) main_kernel(
    const float* __restrict__ x,
    const float* __restrict__ w00, const float* __restrict__ b00,
    const float* __restrict__ w01, const float* __restrict__ b01,
    const float* __restrict__ w02, const float* __restrict__ b02,
    float* __restrict__ out) {
    extern __shared__ float sm[];
    int tile = blockIdx.x, b = blockIdx.y;
    int tid = threadIdx.x;
    int tstart = tile * TILE;

    float* xs = sm + OFF_XS;
    float* f0 = sm + OFF_F0;
    float* w00s = sm + OFF_W00;
    float* w01s = sm + OFF_W01;
    float* w02s = sm + OFF_W02;
    float* mef = sm + OFF_ME;
    float* stg = sm + OFF_STG;
    float* w1fs = sm + OFF_W1F;
    float* b1fs = sm + OFF_B1F;
    float* b2fs = sm + OFF_B2F;
    float* b00s = sm + OFF_B00;
    float* b01s = sm + OFF_B01;
    float* b02s = sm + OFF_B02;

    // ---- load weights in channel-PAIR layout: [cp][128][2] ----
    for (int t = tid; t < 512; t += 256) {
        int cp = t >> 7, rest = t & 127;
        w00s[2 * t]     = w00[(2 * cp) * 128 + rest];
        w00s[2 * t + 1] = w00[(2 * cp + 1) * 128 + rest];
        w01s[2 * t]     = w01[(2 * cp) * 128 + rest];
        w01s[2 * t + 1] = w01[(2 * cp + 1) * 128 + rest];
        w02s[2 * t]     = w02[(2 * cp) * 128 + rest];
        w02s[2 * t + 1] = w02[(2 * cp + 1) * 128 + rest];
    }
    if (tid < 8) { b00s[tid] = b00[tid]; b01s[tid] = b01[tid]; b02s[tid] = b02[tid]; }
    if (tid < 64) w1fs[tid] = g_W1f[tid];
    if (tid < 16) { b1fs[tid] = g_b1f[tid]; b2fs[tid] = g_b2f[tid]; }
    mef[tid] = g_Meff[b * 256 + tid];

    const float* xb = x + (size_t)b * 4 * Lz;
    for (int t = tid; t < 4 * 608; t += 256) {
        int i = t / 608, p = t - i * 608;   // raw p in [0,608)
        int gq = tstart - 30 + p;           // xs[i][SWZ(p)] = x[i][tstart-30+p]
        xs[i * XS_N + SWZ(p)] = (gq >= 0 && gq < Lz) ? xb[i * Lz + gq] : 0.f;
    }
    __syncthreads();

    const ull* w00dd = (const ull*)w00s;
    const ull* w01dd = (const ull*)w01s;
    const ull* w02dd = (const ull*)w02s;

    int o = tid >> 5, g = tid & 31;

    // ---- Phase C: fea0, channel-paired FFMA2. warp o -> cp=o>>1, half=o&1.
    // Lane covers 9 positions fb..fb+8 for channels (2cp, 2cp+1).
    {
        int cp = o >> 1, half = o & 1;
        int fb = (half * 32 + g) * 9;     // fb in [0,567]
        ull acc2[9];
        {
            ull bp = ((const ull*)b00s)[cp];
#pragma unroll
            for (int p = 0; p < 9; p++) acc2[p] = bp;
        }
#pragma unroll
        for (int i = 0; i < 4; i++) {
            const float* xr = xs + i * XS_N;
#pragma unroll
            for (int h = 0; h < 2; h++) {       // k-halves: [0,16), [16,32)
                ull P[24];
#pragma unroll
                for (int t = 0; t < 24; t++) P[t] = bc2(xr[SWZ(fb + 16 * h + t)]);
#pragma unroll
                for (int kk = 0; kk < 16; kk++) {
                    ull wd = w00dd[cp * 128 + i * 32 + 16 * h + kk];
#pragma unroll
                    for (int p = 0; p < 9; p++)
                        acc2[p] = ffma2(P[p + kk], wd, acc2[p]);
                }
            }
        }
#pragma unroll
        for (int p = 0; p < 9; p++) {
            int f = fb + p;
            if (f < 558) {
                int pg = tstart - 14 + f;
                bool valid = (pg >= 0 && pg <= Lz);
                float lo, hi;
                upk2(acc2[p], lo, hi);
                f0[(2 * cp) * FE_STR + SWZ4(f)]     = valid ? lo : 0.f;
                f0[(2 * cp + 1) * FE_STR + SWZ4(f)] = valid ? hi : 0.f;
            }
        }
    }
    __syncthreads();

    // ---- Phase D: warps 0-3 fea1 channel-pairs, warps 4-7 fea2 channel-pairs ----
    if (o < 4) {
        int cp = o;
        ull a1[16];
        {
            ull bp = ((const ull*)b01s)[cp];
#pragma unroll
            for (int p = 0; p < 16; p++) a1[p] = bp;
        }
#pragma unroll
        for (int j = 0; j < 8; j++) {
            const float4* f4 = (const float4*)(f0 + j * FE_STR) + 5 * g;
#pragma unroll
            for (int h = 0; h < 2; h++) {   // k-halves [0,8), [8,16)
                float wt[28];
                int r0 = 4 + 8 * h;
#pragma unroll
                for (int u = 0; u < 7; u++) {
                    int r = r0 + 4 * u;
                    float4 q = f4[5 * (r >> 4) + ((r & 15) >> 2)];
                    wt[4 * u] = q.x; wt[4 * u + 1] = q.y;
                    wt[4 * u + 2] = q.z; wt[4 * u + 3] = q.w;
                }
                ull P[24];
                int t0 = 7 + 8 * h;
#pragma unroll
                for (int t = 0; t < 24; t++) P[t] = bc2(wt[t0 - r0 + t]);
#pragma unroll
                for (int kk = 0; kk < 8; kk++) {
                    ull wd = w01dd[cp * 128 + j * 16 + 8 * h + kk];
#pragma unroll
                    for (int p = 0; p < 16; p++)
                        a1[p] = ffma2(P[p + kk], wd, a1[p]);   // fea1: win[p+k+7]
                }
            }
        }
#pragma unroll
        for (int p = 0; p < 16; p++) {
            int l = g * 16 + p;
            float lo, hi;
            upk2(a1[p], lo, hi);
            stg[(2 * cp) * ST_STR + SWZ(l)]     = lo;
            stg[(2 * cp + 1) * ST_STR + SWZ(l)] = hi;
        }
    } else {
        int cp = o - 4;
        ull a2[16];
        {
            ull bp = ((const ull*)b02s)[cp];
#pragma unroll
            for (int p = 0; p < 16; p++) a2[p] = bp;
        }
#pragma unroll
        for (int j = 0; j < 8; j++) {
            const float4* f4 = (const float4*)(f0 + j * FE_STR) + 5 * g;
#pragma unroll
            for (int c4 = 0; c4 < 4; c4++) {   // k-chunks of 4: [4c4, 4c4+4)
                float wt[24];
                int r0 = 8 * c4;
#pragma unroll
                for (int u = 0; u < 6; u++) {
                    int r = r0 + 4 * u;
                    float4 q = f4[5 * (r >> 4) + ((r & 15) >> 2)];
                    wt[4 * u] = q.x; wt[4 * u + 1] = q.y;
                    wt[4 * u + 2] = q.z; wt[4 * u + 3] = q.w;
                }
                ull P[23];
#pragma unroll
                for (int t = 0; t < 23; t++) P[t] = bc2(wt[t]);
#pragma unroll
                for (int kk = 0; kk < 4; kk++) {
                    ull wd = w02dd[cp * 128 + j * 16 + 4 * c4 + kk];
#pragma unroll
                    for (int p = 0; p < 16; p++)
                        a2[p] = ffma2(P[p + 2 * kk], wd, a2[p]);  // fea2: win[p+2k]
                }
            }
        }
#pragma unroll
        for (int p = 0; p < 16; p++) {
            int l = g * 16 + p;
            int gl = tstart + l;
            bool inb = (gl >= 1 && gl <= 8189);   // fea2 pad(1,2): 0 at l==0, l>=8190
            float lo, hi;
            upk2(a2[p], lo, hi);
            stg[(8 + 2 * cp) * ST_STR + SWZ(l)]     = inb ? lo : 0.f;
            stg[(8 + 2 * cp + 1) * ST_STR + SWZ(l)] = inb ? hi : 0.f;
        }
    }
    __syncthreads();

    // ---- Phase F: c0 -> c2 = relu(Meff@c0 + b2f), add conv, store ----
#pragma unroll
    for (int it = 0; it < 2; it++) {
        int loc = tid + it * 256;
        int gl = tstart + loc;
        float xv[4];
#pragma unroll
        for (int i = 0; i < 4; i++) xv[i] = xs[i * XS_N + SWZ(loc + 30)];
        float c0[16];
#pragma unroll
        for (int d = 0; d < 16; d++) {
            float s = b1fs[d];
#pragma unroll
            for (int i = 0; i < 4; i++) s += xv[i] * w1fs[d * 4 + i];
            c0[d] = fmaxf(s, 0.f);
        }
#pragma unroll
        for (int c = 0; c < 16; c++) {
            float a = b2fs[c];
#pragma unroll
            for (int d = 0; d < 16; d++) a += mef[c * 16 + d] * c0[d];
            a = fmaxf(a, 0.f);
            out[((size_t)b * 16 + c) * Lz + gl] = stg[c * ST_STR + SWZ(loc)] + a;
        }
    }
}

// ---------------- launch ----------------
extern "C" void kernel_launch(void* const* d_in, const int* in_sizes, int n_in,
                              void* d_out, int out_size) {
    const float* x    = (const float*)d_in[0];
    const float* w00  = (const float*)d_in[1];
    const float* b00  = (const float*)d_in[2];
    const float* w01  = (const float*)d_in[3];
    const float* b01  = (const float*)d_in[4];
    const float* w02  = (const float*)d_in[5];
    const float* b02  = (const float*)d_in[6];
    const float* wc1  = (const float*)d_in[7];
    const float* g1   = (const float*)d_in[8];
    const float* bt1  = (const float*)d_in[9];
    const float* m1   = (const float*)d_in[10];
    const float* v1   = (const float*)d_in[11];
    const float* beta = (const float*)d_in[12];
    const float* wc2  = (const float*)d_in[13];
    const float* g2   = (const float*)d_in[14];
    const float* bt2  = (const float*)d_in[15];
    const float* m2   = (const float*)d_in[16];
    const float* v2   = (const float*)d_in[17];
    float* out = (float*)d_out;

    cudaFuncSetAttribute(main_kernel, cudaFuncAttributeMaxDynamicSharedMemorySize,
                         SMEM_FLOATS * 4);

    prep_kernel<<<1, 64>>>(wc1, g1, bt1, m1, v1, g2, bt2, m2, v2);
    gram_attn_kernel<<<Bz, 256>>>(x, wc2, g2, v2, beta);
    main_kernel<<<dim3(Lz / TILE, Bz), 256, SMEM_FLOATS * 4>>>(
        x, w00, b00, w01, b01, w02, b02, out);
}

// round 8
// speedup vs baseline: 1.2054x; 1.2054x over previous
#include <cuda_runtime.h>

#define Bz 256
#define Lz 8192
#define EPSf 1e-5f

// ---------------- scratch (no allocs allowed) ----------------
__device__ float g_Meff[Bz * 256];

// triangular index for c<=d
#define TRI(c, d) ((c)*16 - ((c) * ((c) + 1)) / 2 + (d))

// ---------------- gram + attn fused: one CTA per batch ----------------
__global__ void __launch_bounds__(256) gram_attn_kernel(
    const float* __restrict__ x, const float* __restrict__ wc1,
    const float* __restrict__ g1, const float* __restrict__ bt1,
    const float* __restrict__ m1, const float* __restrict__ v1,
    const float* __restrict__ wc2, const float* __restrict__ g2,
    const float* __restrict__ v2, const float* __restrict__ beta_cam) {
    int b = blockIdx.x;
    int tid = threadIdx.x;
    __shared__ float w1fs[64], b1fs[16];
    __shared__ float wsum[8][136];
    __shared__ float gram_s[256];
    __shared__ float As[256];
    if (tid < 64) {
        int d = tid >> 2;
        float s1 = g1[d] * rsqrtf(v1[d] + EPSf);
        w1fs[tid] = wc1[tid] * s1;
        if ((tid & 3) == 0) b1fs[d] = bt1[d] - m1[d] * s1;
    }
    __syncthreads();

    float acc[136];
#pragma unroll
    for (int t = 0; t < 136; t++) acc[t] = 0.f;

    const float* xb = x + (size_t)b * 4 * Lz;
    for (int it = 0; it < 32; it++) {
        int pos = it * 256 + tid;
        float xv0 = xb[0 * Lz + pos];
        float xv1 = xb[1 * Lz + pos];
        float xv2 = xb[2 * Lz + pos];
        float xv3 = xb[3 * Lz + pos];
        float c0[16];
#pragma unroll
        for (int d = 0; d < 16; d++) {
            float s = b1fs[d];
            s += xv0 * w1fs[d * 4 + 0];
            s += xv1 * w1fs[d * 4 + 1];
            s += xv2 * w1fs[d * 4 + 2];
            s += xv3 * w1fs[d * 4 + 3];
            c0[d] = fmaxf(s, 0.f);
        }
#pragma unroll
        for (int c = 0; c < 16; c++)
#pragma unroll
            for (int d = c; d < 16; d++)
                acc[TRI(c, d)] += c0[c] * c0[d];
    }

    int warp = tid >> 5, lane = tid & 31;
#pragma unroll
    for (int t = 0; t < 136; t++) {
        float v = acc[t];
        v += __shfl_xor_sync(0xffffffffu, v, 16);
        v += __shfl_xor_sync(0xffffffffu, v, 8);
        v += __shfl_xor_sync(0xffffffffu, v, 4);
        v += __shfl_xor_sync(0xffffffffu, v, 2);
        v += __shfl_xor_sync(0xffffffffu, v, 1);
        if (lane == 0) wsum[warp][t] = v;
    }
    __syncthreads();
    if (tid < 136) {
        float s = 0.f;
#pragma unroll
        for (int w = 0; w < 8; w++) s += wsum[w][tid];
        int c = 0, rem = tid;
        while (rem >= 16 - c) { rem -= 16 - c; c++; }
        int d = c + rem;
        gram_s[c * 16 + d] = s;
        if (d != c) gram_s[d * 16 + c] = s;
    }
    __syncthreads();

    // ---- attn: softmax(rowmax - gram) folded into Meff ----
    float g = gram_s[tid];
    float mn = g;
    mn = fminf(mn, __shfl_xor_sync(0xffffffffu, mn, 8, 16));
    mn = fminf(mn, __shfl_xor_sync(0xffffffffu, mn, 4, 16));
    mn = fminf(mn, __shfl_xor_sync(0xffffffffu, mn, 2, 16));
    mn = fminf(mn, __shfl_xor_sync(0xffffffffu, mn, 1, 16));
    float e = expf(mn - g);
    float s = e;
    s += __shfl_xor_sync(0xffffffffu, s, 8, 16);
    s += __shfl_xor_sync(0xffffffffu, s, 4, 16);
    s += __shfl_xor_sync(0xffffffffu, s, 2, 16);
    s += __shfl_xor_sync(0xffffffffu, s, 1, 16);
    float beta = beta_cam[0];
    As[tid] = beta * (e / s);
    __syncthreads();

    int c = tid >> 4, d = tid & 15;
    float s2c = g2[c] * rsqrtf(v2[c] + EPSf);
    float a = wc2[c * 16 + d];
#pragma unroll
    for (int e2 = 0; e2 < 16; e2++)
        a += wc2[c * 16 + e2] * As[e2 * 16 + d];
    g_Meff[b * 256 + tid] = s2c * a;
}

// ---------------- fused main kernel ----------------
#define TILE 512
#define XS_N 648          // x tile + halo, swizzled (raw 607 -> swz 644)
#define FE_STR 704        // fea0 per-channel stride (raw 557 -> SWZ4 693), 16B-mult
#define ST_STR 544        // stage per-channel stride (raw 511 -> swz 542)
#define SWZ(i) ((i) + ((i) >> 4))
#define SWZ4(i) ((i) + (((i) >> 4) << 2))

#define OFF_XS 0
#define OFF_F0 (OFF_XS + 4 * XS_N)            // 2592
#define OFF_W00 (OFF_F0 + 8 * FE_STR)         // 8224
#define OFF_W01 (OFF_W00 + 1024)              // 9248
#define OFF_W02 (OFF_W01 + 1024)              // 10272
#define OFF_ME (OFF_W02 + 1024)               // 11296
#define OFF_STG (OFF_ME + 256)                // 11552
#define OFF_W1F (OFF_STG + 16 * ST_STR)       // 20256
#define OFF_B1F (OFF_W1F + 64)                // 20320
#define OFF_B2F (OFF_B1F + 16)                // 20336
#define OFF_B00 (OFF_B2F + 16)                // 20352
#define OFF_B01 (OFF_B00 + 8)                 // 20360
#define OFF_B02 (OFF_B01 + 8)                 // 20368
#define SMEM_FLOATS (OFF_B02 + 8)             // 20376 floats = 81504 B

__global__ void __launch_bounds__(256, 2) main_kernel(
    const float* __restrict__ x,
    const float* __restrict__ w00, const float* __restrict__ b00,
    const float* __restrict__ w01, const float* __restrict__ b01,
    const float* __restrict__ w02, const float* __restrict__ b02,
    const float* __restrict__ wc1, const float* __restrict__ g1,
    const float* __restrict__ bt1, const float* __restrict__ m1,
    const float* __restrict__ v1, const float* __restrict__ g2,
    const float* __restrict__ bt2, const float* __restrict__ m2,
    const float* __restrict__ v2,
    float* __restrict__ out) {
    extern __shared__ float sm[];
    int tile = blockIdx.x, b = blockIdx.y;
    int tid = threadIdx.x;
    int tstart = tile * TILE;

    float* xs = sm + OFF_XS;
    float* f0 = sm + OFF_F0;
    float* w00s = sm + OFF_W00;
    float* w01s = sm + OFF_W01;
    float* w02s = sm + OFF_W02;
    float* mef = sm + OFF_ME;
    float* stg = sm + OFF_STG;
    float* w1fs = sm + OFF_W1F;
    float* b1fs = sm + OFF_B1F;
    float* b2fs = sm + OFF_B2F;
    float* b00s = sm + OFF_B00;
    float* b01s = sm + OFF_B01;
    float* b02s = sm + OFF_B02;

    // ---- load weights + fold BN locally + x tile (xs stored swizzled) ----
    for (int t = tid; t < 1024; t += 256) {
        w00s[t] = w00[t];
        w01s[t] = w01[t];
        w02s[t] = w02[t];
    }
    if (tid < 8) { b00s[tid] = b00[tid]; b01s[tid] = b01[tid]; b02s[tid] = b02[tid]; }
    if (tid < 64) {
        int d = tid >> 2;
        float s1 = g1[d] * rsqrtf(v1[d] + EPSf);
        w1fs[tid] = wc1[tid] * s1;
        if ((tid & 3) == 0) b1fs[d] = bt1[d] - m1[d] * s1;
    }
    if (tid < 16) {
        float s2 = g2[tid] * rsqrtf(v2[tid] + EPSf);
        b2fs[tid] = bt2[tid] - m2[tid] * s2;
    }
    mef[tid] = g_Meff[b * 256 + tid];

    const float* xb = x + (size_t)b * 4 * Lz;
    for (int t = tid; t < 4 * 608; t += 256) {
        int i = t / 608, p = t - i * 608;   // raw p in [0,608)
        int gq = tstart - 30 + p;           // xs[i][SWZ(p)] = x[i][tstart-30+p]
        xs[i * XS_N + SWZ(p)] = (gq >= 0 && gq < Lz) ? xb[i * Lz + gq] : 0.f;
    }
    __syncthreads();

    int o = tid >> 5, g = tid & 31;  // warp-uniform o -> weight broadcast

    // ---- Phase C: fea0[o][f], f in [0,558), 18 positions/lane ----
    {
        float acc[18];
#pragma unroll
        for (int p = 0; p < 18; p++) acc[p] = b00s[o];
#pragma unroll
        for (int i = 0; i < 4; i++) {
            const float* xr = xs + i * XS_N;
            float win[49];
#pragma unroll
            for (int t = 0; t < 49; t++) {
                int p = g * 18 + t;
                win[t] = xr[SWZ(p)];
            }
#pragma unroll
            for (int k = 0; k < 32; k++) {
                float w = w00s[o * 128 + i * 32 + k];
#pragma unroll
                for (int p = 0; p < 18; p++) acc[p] += win[p + k] * w;
            }
        }
#pragma unroll
        for (int p = 0; p < 18; p++) {
            int f = g * 18 + p;
            if (f < 558) {
                int pg = tstart - 14 + f;
                f0[o * FE_STR + SWZ4(f)] = (pg >= 0 && pg <= Lz) ? acc[p] : 0.f;
            }
        }
    }
    __syncthreads();

    // ---- Phase D: fea1 & fea2 via sliding window, float4 window loads ----
    {
        float a1[16], a2[16];
#pragma unroll
        for (int p = 0; p < 16; p++) { a1[p] = b01s[o]; a2[p] = b02s[o]; }
#pragma unroll
        for (int j = 0; j < 8; j++) {
            // window covers raw f0 indices [16g, 16g+46); SWZ4 maps 16-blocks
            // to contiguous 16B-aligned runs at 20g, 20g+20, 20g+40.
            const float4* f4 = (const float4*)(f0 + j * FE_STR + 20 * g);
            float win[46];
            float4 q;
            q = f4[0];  win[0] = q.x;  win[1] = q.y;  win[2] = q.z;  win[3] = q.w;
            q = f4[1];  win[4] = q.x;  win[5] = q.y;  win[6] = q.z;  win[7] = q.w;
            q = f4[2];  win[8] = q.x;  win[9] = q.y;  win[10] = q.z; win[11] = q.w;
            q = f4[3];  win[12] = q.x; win[13] = q.y; win[14] = q.z; win[15] = q.w;
            q = f4[5];  win[16] = q.x; win[17] = q.y; win[18] = q.z; win[19] = q.w;
            q = f4[6];  win[20] = q.x; win[21] = q.y; win[22] = q.z; win[23] = q.w;
            q = f4[7];  win[24] = q.x; win[25] = q.y; win[26] = q.z; win[27] = q.w;
            q = f4[8];  win[28] = q.x; win[29] = q.y; win[30] = q.z; win[31] = q.w;
            q = f4[10]; win[32] = q.x; win[33] = q.y; win[34] = q.z; win[35] = q.w;
            q = f4[11]; win[36] = q.x; win[37] = q.y; win[38] = q.z; win[39] = q.w;
            q = f4[12]; win[40] = q.x; win[41] = q.y; win[42] = q.z; win[43] = q.w;
            q = f4[13]; win[44] = q.x; win[45] = q.y;
#pragma unroll
            for (int k = 0; k < 16; k++) {
                float w1 = w01s[o * 128 + j * 16 + k];
                float w2 = w02s[o * 128 + j * 16 + k];
#pragma unroll
                for (int p = 0; p < 16; p++) {
                    a1[p] += win[p + k + 7] * w1;   // fea1: fea0[l+k-7]
                    a2[p] += win[p + 2 * k] * w2;   // fea2 padded: fea0[l-14+2k]
                }
            }
        }
#pragma unroll
        for (int p = 0; p < 16; p++) {
            int l = g * 16 + p;
            int gl = tstart + l;
            stg[o * ST_STR + SWZ(l)] = a1[p];
            // fea2 after pad(1,2): exactly 0 at l==0 and l>=8190
            stg[(8 + o) * ST_STR + SWZ(l)] = (gl >= 1 && gl <= 8189) ? a2[p] : 0.f;
        }
    }
    __syncthreads();

    // ---- Phase F: c0 -> c2 = relu(Meff@c0 + b2f), add conv, store ----
#pragma unroll
    for (int it = 0; it < 2; it++) {
        int loc = tid + it * 256;
        int gl = tstart + loc;
        float xv[4];
#pragma unroll
        for (int i = 0; i < 4; i++) xv[i] = xs[i * XS_N + SWZ(loc + 30)];
        float c0[16];
#pragma unroll
        for (int d = 0; d < 16; d++) {
            float s = b1fs[d];
#pragma unroll
            for (int i = 0; i < 4; i++) s += xv[i] * w1fs[d * 4 + i];
            c0[d] = fmaxf(s, 0.f);
        }
#pragma unroll
        for (int c = 0; c < 16; c++) {
            float a = b2fs[c];
#pragma unroll
            for (int d = 0; d < 16; d++) a += mef[c * 16 + d] * c0[d];
            a = fmaxf(a, 0.f);
            out[((size_t)b * 16 + c) * Lz + gl] = stg[c * ST_STR + SWZ(loc)] + a;
        }
    }
}

// ---------------- launch ----------------
extern "C" void kernel_launch(void* const* d_in, const int* in_sizes, int n_in,
                              void* d_out, int out_size) {
    const float* x    = (const float*)d_in[0];
    const float* w00  = (const float*)d_in[1];
    const float* b00  = (const float*)d_in[2];
    const float* w01  = (const float*)d_in[3];
    const float* b01  = (const float*)d_in[4];
    const float* w02  = (const float*)d_in[5];
    const float* b02  = (const float*)d_in[6];
    const float* wc1  = (const float*)d_in[7];
    const float* g1   = (const float*)d_in[8];
    const float* bt1  = (const float*)d_in[9];
    const float* m1   = (const float*)d_in[10];
    const float* v1   = (const float*)d_in[11];
    const float* beta = (const float*)d_in[12];
    const float* wc2  = (const float*)d_in[13];
    const float* g2   = (const float*)d_in[14];
    const float* bt2  = (const float*)d_in[15];
    const float* m2   = (const float*)d_in[16];
    const float* v2   = (const float*)d_in[17];
    float* out = (float*)d_out;

    cudaFuncSetAttribute(main_kernel, cudaFuncAttributeMaxDynamicSharedMemorySize,
                         SMEM_FLOATS * 4);

    gram_attn_kernel<<<Bz, 256>>>(x, wc1, g1, bt1, m1, v1, wc2, g2, v2, beta);
    main_kernel<<<dim3(Lz / TILE, Bz), 256, SMEM_FLOATS * 4>>>(
        x, w00, b00, w01, b01, w02, b02,
        wc1, g1, bt1, m1, v1, g2, bt2, m2, v2, out);
}

// round 9
// speedup vs baseline: 1.2063x; 1.0007x over previous
#include <cuda_runtime.h>

#define Bz 256
#define Lz 8192
#define EPSf 1e-5f

// ---------------- scratch (no allocs allowed) ----------------
__device__ float g_Meff[Bz * 256];

// triangular index for c<=d
#define TRI(c, d) ((c)*16 - ((c) * ((c) + 1)) / 2 + (d))

// ---------------- gram + attn fused: one CTA per batch ----------------
__global__ void __launch_bounds__(256) gram_attn_kernel(
    const float* __restrict__ x, const float* __restrict__ wc1,
    const float* __restrict__ g1, const float* __restrict__ bt1,
    const float* __restrict__ m1, const float* __restrict__ v1,
    const float* __restrict__ wc2, const float* __restrict__ g2,
    const float* __restrict__ v2, const float* __restrict__ beta_cam) {
    int b = blockIdx.x;
    int tid = threadIdx.x;
    __shared__ float w1fs[64], b1fs[16];
    __shared__ float wsum[8][136];
    __shared__ float gram_s[256];
    __shared__ float As[256];
    if (tid < 64) {
        int d = tid >> 2;
        float s1 = g1[d] * rsqrtf(v1[d] + EPSf);
        w1fs[tid] = wc1[tid] * s1;
        if ((tid & 3) == 0) b1fs[d] = bt1[d] - m1[d] * s1;
    }
    __syncthreads();

    float acc[136];
#pragma unroll
    for (int t = 0; t < 136; t++) acc[t] = 0.f;

    const float* xb = x + (size_t)b * 4 * Lz;
    for (int it = 0; it < 32; it++) {
        int pos = it * 256 + tid;
        float xv0 = xb[0 * Lz + pos];
        float xv1 = xb[1 * Lz + pos];
        float xv2 = xb[2 * Lz + pos];
        float xv3 = xb[3 * Lz + pos];
        float c0[16];
#pragma unroll
        for (int d = 0; d < 16; d++) {
            float s = b1fs[d];
            s += xv0 * w1fs[d * 4 + 0];
            s += xv1 * w1fs[d * 4 + 1];
            s += xv2 * w1fs[d * 4 + 2];
            s += xv3 * w1fs[d * 4 + 3];
            c0[d] = fmaxf(s, 0.f);
        }
#pragma unroll
        for (int c = 0; c < 16; c++)
#pragma unroll
            for (int d = c; d < 16; d++)
                acc[TRI(c, d)] += c0[c] * c0[d];
    }

    int warp = tid >> 5, lane = tid & 31;
#pragma unroll
    for (int t = 0; t < 136; t++) {
        float v = acc[t];
        v += __shfl_xor_sync(0xffffffffu, v, 16);
        v += __shfl_xor_sync(0xffffffffu, v, 8);
        v += __shfl_xor_sync(0xffffffffu, v, 4);
        v += __shfl_xor_sync(0xffffffffu, v, 2);
        v += __shfl_xor_sync(0xffffffffu, v, 1);
        if (lane == 0) wsum[warp][t] = v;
    }
    __syncthreads();
    if (tid < 136) {
        float s = 0.f;
#pragma unroll
        for (int w = 0; w < 8; w++) s += wsum[w][tid];
        int c = 0, rem = tid;
        while (rem >= 16 - c) { rem -= 16 - c; c++; }
        int d = c + rem;
        gram_s[c * 16 + d] = s;
        if (d != c) gram_s[d * 16 + c] = s;
    }
    __syncthreads();

    // ---- attn: softmax(rowmax - gram) folded into Meff ----
    float g = gram_s[tid];
    float mn = g;
    mn = fminf(mn, __shfl_xor_sync(0xffffffffu, mn, 8, 16));
    mn = fminf(mn, __shfl_xor_sync(0xffffffffu, mn, 4, 16));
    mn = fminf(mn, __shfl_xor_sync(0xffffffffu, mn, 2, 16));
    mn = fminf(mn, __shfl_xor_sync(0xffffffffu, mn, 1, 16));
    float e = expf(mn - g);
    float s = e;
    s += __shfl_xor_sync(0xffffffffu, s, 8, 16);
    s += __shfl_xor_sync(0xffffffffu, s, 4, 16);
    s += __shfl_xor_sync(0xffffffffu, s, 2, 16);
    s += __shfl_xor_sync(0xffffffffu, s, 1, 16);
    float beta = beta_cam[0];
    As[tid] = beta * (e / s);
    __syncthreads();

    int c = tid >> 4, d = tid & 15;
    float s2c = g2[c] * rsqrtf(v2[c] + EPSf);
    float a = wc2[c * 16 + d];
#pragma unroll
    for (int e2 = 0; e2 < 16; e2++)
        a += wc2[c * 16 + e2] * As[e2 * 16 + d];
    g_Meff[b * 256 + tid] = s2c * a;
}

// ---------------- fused main kernel ----------------
#define TILE 512
#define XS_N 648          // x tile + halo, swizzled (raw 607 -> swz 644)
#define FE_STR 704        // fea0 per-channel stride (raw 557 -> SWZ4 693), 16B-mult
#define ST_STR 544        // stage per-channel stride (raw 511 -> swz 542)
#define SWZ(i) ((i) + ((i) >> 4))
#define SWZ4(i) ((i) + (((i) >> 4) << 2))

#define OFF_XS 0
#define OFF_F0 (OFF_XS + 4 * XS_N)            // 2592
#define OFF_W00 (OFF_F0 + 8 * FE_STR)         // 8224
#define OFF_W01 (OFF_W00 + 1024)              // 9248
#define OFF_W02 (OFF_W01 + 1024)              // 10272
#define OFF_ME (OFF_W02 + 1024)               // 11296
#define OFF_STG (OFF_ME + 256)                // 11552
#define OFF_W1F (OFF_STG + 16 * ST_STR)       // 20256
#define OFF_B1F (OFF_W1F + 64)                // 20320
#define OFF_B2F (OFF_B1F + 16)                // 20336
#define OFF_B00 (OFF_B2F + 16)                // 20352
#define OFF_B01 (OFF_B00 + 8)                 // 20360
#define OFF_B02 (OFF_B01 + 8)                 // 20368
#define SMEM_FLOATS (OFF_B02 + 8)             // 20376 floats = 81504 B

__global__ void __launch_bounds__(256, 2) main_kernel(
    const float* __restrict__ x,
    const float* __restrict__ w00, const float* __restrict__ b00,
    const float* __restrict__ w01, const float* __restrict__ b01,
    const float* __restrict__ w02, const float* __restrict__ b02,
    const float* __restrict__ wc1, const float* __restrict__ g1,
    const float* __restrict__ bt1, const float* __restrict__ m1,
    const float* __restrict__ v1, const float* __restrict__ g2,
    const float* __restrict__ bt2, const float* __restrict__ m2,
    const float* __restrict__ v2,
    float* __restrict__ out) {
    extern __shared__ float sm[];
    int tile = blockIdx.x, b = blockIdx.y;
    int tid = threadIdx.x;
    int tstart = tile * TILE;

    float* xs = sm + OFF_XS;
    float* f0 = sm + OFF_F0;
    float* w00s = sm + OFF_W00;
    float* w01s = sm + OFF_W01;
    float* w02s = sm + OFF_W02;
    float* mef = sm + OFF_ME;
    float* stg = sm + OFF_STG;
    float* w1fs = sm + OFF_W1F;
    float* b1fs = sm + OFF_B1F;
    float* b2fs = sm + OFF_B2F;
    float* b00s = sm + OFF_B00;
    float* b01s = sm + OFF_B01;
    float* b02s = sm + OFF_B02;

    // ---- load weights + fold BN locally + x tile (xs stored swizzled) ----
    for (int t = tid; t < 1024; t += 256) {
        w00s[t] = w00[t];
        w01s[t] = w01[t];
        w02s[t] = w02[t];
    }
    if (tid < 8) { b00s[tid] = b00[tid]; b01s[tid] = b01[tid]; b02s[tid] = b02[tid]; }
    if (tid < 64) {
        int d = tid >> 2;
        float s1 = g1[d] * rsqrtf(v1[d] + EPSf);
        w1fs[tid] = wc1[tid] * s1;
        if ((tid & 3) == 0) b1fs[d] = bt1[d] - m1[d] * s1;
    }
    if (tid < 16) {
        float s2 = g2[tid] * rsqrtf(v2[tid] + EPSf);
        b2fs[tid] = bt2[tid] - m2[tid] * s2;
    }
    mef[tid] = g_Meff[b * 256 + tid];

    const float* xb = x + (size_t)b * 4 * Lz;
    for (int t = tid; t < 4 * 608; t += 256) {
        int i = t / 608, p = t - i * 608;   // raw p in [0,608)
        int gq = tstart - 30 + p;           // xs[i][SWZ(p)] = x[i][tstart-30+p]
        xs[i * XS_N + SWZ(p)] = (gq >= 0 && gq < Lz) ? xb[i * Lz + gq] : 0.f;
    }
    __syncthreads();

    int o = tid >> 5, g = tid & 31;  // warp-uniform o -> weight broadcast

    // ---- Phase C: fea0[o][f], f in [0,558), 18 positions/lane ----
    {
        float acc[18];
#pragma unroll
        for (int p = 0; p < 18; p++) acc[p] = b00s[o];
#pragma unroll
        for (int i = 0; i < 4; i++) {
            const float* xr = xs + i * XS_N;
            float win[49];
#pragma unroll
            for (int t = 0; t < 49; t++) {
                int p = g * 18 + t;
                win[t] = xr[SWZ(p)];
            }
            const float4* wv = (const float4*)(w00s + o * 128 + i * 32);
#pragma unroll
            for (int kq = 0; kq < 8; kq++) {
                float4 wq = wv[kq];
#pragma unroll
                for (int p = 0; p < 18; p++) acc[p] += win[p + 4 * kq + 0] * wq.x;
#pragma unroll
                for (int p = 0; p < 18; p++) acc[p] += win[p + 4 * kq + 1] * wq.y;
#pragma unroll
                for (int p = 0; p < 18; p++) acc[p] += win[p + 4 * kq + 2] * wq.z;
#pragma unroll
                for (int p = 0; p < 18; p++) acc[p] += win[p + 4 * kq + 3] * wq.w;
            }
        }
#pragma unroll
        for (int p = 0; p < 18; p++) {
            int f = g * 18 + p;
            if (f < 558) {
                int pg = tstart - 14 + f;
                f0[o * FE_STR + SWZ4(f)] = (pg >= 0 && pg <= Lz) ? acc[p] : 0.f;
            }
        }
    }
    __syncthreads();

    // ---- Phase D: fea1 & fea2 via sliding window, float4 window+weight loads ----
    {
        float a1[16], a2[16];
#pragma unroll
        for (int p = 0; p < 16; p++) { a1[p] = b01s[o]; a2[p] = b02s[o]; }
#pragma unroll
        for (int j = 0; j < 8; j++) {
            // window covers raw f0 indices [16g, 16g+46); SWZ4 maps 16-blocks
            // to contiguous 16B-aligned runs at 20g, 20g+20, 20g+40.
            const float4* f4 = (const float4*)(f0 + j * FE_STR + 20 * g);
            float win[46];
            float4 q;
            q = f4[0];  win[0] = q.x;  win[1] = q.y;  win[2] = q.z;  win[3] = q.w;
            q = f4[1];  win[4] = q.x;  win[5] = q.y;  win[6] = q.z;  win[7] = q.w;
            q = f4[2];  win[8] = q.x;  win[9] = q.y;  win[10] = q.z; win[11] = q.w;
            q = f4[3];  win[12] = q.x; win[13] = q.y; win[14] = q.z; win[15] = q.w;
            q = f4[5];  win[16] = q.x; win[17] = q.y; win[18] = q.z; win[19] = q.w;
            q = f4[6];  win[20] = q.x; win[21] = q.y; win[22] = q.z; win[23] = q.w;
            q = f4[7];  win[24] = q.x; win[25] = q.y; win[26] = q.z; win[27] = q.w;
            q = f4[8];  win[28] = q.x; win[29] = q.y; win[30] = q.z; win[31] = q.w;
            q = f4[10]; win[32] = q.x; win[33] = q.y; win[34] = q.z; win[35] = q.w;
            q = f4[11]; win[36] = q.x; win[37] = q.y; win[38] = q.z; win[39] = q.w;
            q = f4[12]; win[40] = q.x; win[41] = q.y; win[42] = q.z; win[43] = q.w;
            q = f4[13]; win[44] = q.x; win[45] = q.y;
            const float4* w1v = (const float4*)(w01s + o * 128 + j * 16);
            const float4* w2v = (const float4*)(w02s + o * 128 + j * 16);
#pragma unroll
            for (int kq = 0; kq < 4; kq++) {
                float4 w1q = w1v[kq];
                float4 w2q = w2v[kq];
                int k0 = 4 * kq;
#pragma unroll
                for (int p = 0; p < 16; p++) {
                    a1[p] += win[p + k0 + 7] * w1q.x;
                    a2[p] += win[p + 2 * k0] * w2q.x;
                }
#pragma unroll
                for (int p = 0; p < 16; p++) {
                    a1[p] += win[p + k0 + 8] * w1q.y;
                    a2[p] += win[p + 2 * k0 + 2] * w2q.y;
                }
#pragma unroll
                for (int p = 0; p < 16; p++) {
                    a1[p] += win[p + k0 + 9] * w1q.z;
                    a2[p] += win[p + 2 * k0 + 4] * w2q.z;
                }
#pragma unroll
                for (int p = 0; p < 16; p++) {
                    a1[p] += win[p + k0 + 10] * w1q.w;
                    a2[p] += win[p + 2 * k0 + 6] * w2q.w;
                }
            }
        }
#pragma unroll
        for (int p = 0; p < 16; p++) {
            int l = g * 16 + p;
            int gl = tstart + l;
            stg[o * ST_STR + SWZ(l)] = a1[p];
            // fea2 after pad(1,2): exactly 0 at l==0 and l>=8190
            stg[(8 + o) * ST_STR + SWZ(l)] = (gl >= 1 && gl <= 8189) ? a2[p] : 0.f;
        }
    }
    __syncthreads();

    // ---- Phase F: c0 -> c2 = relu(Meff@c0 + b2f), add conv, store ----
#pragma unroll
    for (int it = 0; it < 2; it++) {
        int loc = tid + it * 256;
        int gl = tstart + loc;
        float xv[4];
#pragma unroll
        for (int i = 0; i < 4; i++) xv[i] = xs[i * XS_N + SWZ(loc + 30)];
        float c0[16];
#pragma unroll
        for (int d = 0; d < 16; d++) {
            float s = b1fs[d];
#pragma unroll
            for (int i = 0; i < 4; i++) s += xv[i] * w1fs[d * 4 + i];
            c0[d] = fmaxf(s, 0.f);
        }
#pragma unroll
        for (int c = 0; c < 16; c++) {
            const float4* mrow = (const float4*)(mef + c * 16);
            float4 m0 = mrow[0], m1 = mrow[1], m2 = mrow[2], m3 = mrow[3];
            float a = b2fs[c];
            a += m0.x * c0[0];  a += m0.y * c0[1];
            a += m0.z * c0[2];  a += m0.w * c0[3];
            a += m1.x * c0[4];  a += m1.y * c0[5];
            a += m1.z * c0[6];  a += m1.w * c0[7];
            a += m2.x * c0[8];  a += m2.y * c0[9];
            a += m2.z * c0[10]; a += m2.w * c0[11];
            a += m3.x * c0[12]; a += m3.y * c0[13];
            a += m3.z * c0[14]; a += m3.w * c0[15];
            a = fmaxf(a, 0.f);
            out[((size_t)b * 16 + c) * Lz + gl] = stg[c * ST_STR + SWZ(loc)] + a;
        }
    }
}

// ---------------- launch ----------------
extern "C" void kernel_launch(void* const* d_in, const int* in_sizes, int n_in,
                              void* d_out, int out_size) {
    const float* x    = (const float*)d_in[0];
    const float* w00  = (const float*)d_in[1];
    const float* b00  = (const float*)d_in[2];
    const float* w01  = (const float*)d_in[3];
    const float* b01  = (const float*)d_in[4];
    const float* w02  = (const float*)d_in[5];
    const float* b02  = (const float*)d_in[6];
    const float* wc1  = (const float*)d_in[7];
    const float* g1   = (const float*)d_in[8];
    const float* bt1  = (const float*)d_in[9];
    const float* m1   = (const float*)d_in[10];
    const float* v1   = (const float*)d_in[11];
    const float* beta = (const float*)d_in[12];
    const float* wc2  = (const float*)d_in[13];
    const float* g2   = (const float*)d_in[14];
    const float* bt2  = (const float*)d_in[15];
    const float* m2   = (const float*)d_in[16];
    const float* v2   = (const float*)d_in[17];
    float* out = (float*)d_out;

    cudaFuncSetAttribute(main_kernel, cudaFuncAttributeMaxDynamicSharedMemorySize,
                         SMEM_FLOATS * 4);

    gram_attn_kernel<<<Bz, 256>>>(x, wc1, g1, bt1, m1, v1, wc2, g2, v2, beta);
    main_kernel<<<dim3(Lz / TILE, Bz), 256, SMEM_FLOATS * 4>>>(
        x, w00, b00, w01, b01, w02, b02,
        wc1, g1, bt1, m1, v1, g2, bt2, m2, v2, out);
}